// round 16
// baseline (speedup 1.0000x reference)
#include <cuda_runtime.h>
#include <cuda_fp16.h>
#include <cstdint>

// Problem constants
#define B_  2
#define S_  2048
#define H_  1024
#define NH_ 16
#define HD_ 64
#define M_  (B_*S_)   // 4096 rows

// ---------------------------------------------------------------------------
// Scratch (allocation-free: device globals)
// ---------------------------------------------------------------------------
__device__ __half g_Xh[(size_t)M_ * H_];
__device__ __half g_WhT[4][(size_t)H_ * H_];     // transposed [N,K] fp16
__device__ __half g_Qah[(size_t)M_ * H_];        // [b,h,s,d] fp16 (pre-scaled 0.125*log2e)
__device__ __half g_Kah[(size_t)M_ * H_];        // [b,h,s,d] fp16
__device__ __half g_Vth[(size_t)M_ * H_];        // [b,h,d,s] fp16
__device__ __half g_Ch [(size_t)M_ * H_];        // context [s,H] fp16

// ---------------------------------------------------------------------------
// Helpers
// ---------------------------------------------------------------------------
__device__ __forceinline__ uint32_t smem_u32(const void* p) {
    uint32_t a;
    asm("{ .reg .u64 t; cvta.to.shared.u64 t, %1; cvt.u32.u64 %0, t; }"
        : "=r"(a) : "l"(p));
    return a;
}
__device__ __forceinline__ void cp16(uint32_t s, const void* g) {
    asm volatile("cp.async.cg.shared.global [%0], [%1], 16;" :: "r"(s), "l"(g));
}
__device__ __forceinline__ void cp_commit() {
    asm volatile("cp.async.commit_group;" ::: "memory");
}
__device__ __forceinline__ void mma16816(float* c, const uint32_t* a, const uint32_t* b) {
    asm volatile(
        "mma.sync.aligned.m16n8k16.row.col.f32.f16.f16.f32 "
        "{%0,%1,%2,%3}, {%4,%5,%6,%7}, {%8,%9}, {%0,%1,%2,%3};"
        : "+f"(c[0]), "+f"(c[1]), "+f"(c[2]), "+f"(c[3])
        : "r"(a[0]), "r"(a[1]), "r"(a[2]), "r"(a[3]), "r"(b[0]), "r"(b[1]));
}
__device__ __forceinline__ void ldsm_x4(uint32_t* r, uint32_t addr) {
    asm volatile("ldmatrix.sync.aligned.m8n8.x4.shared.b16 {%0,%1,%2,%3}, [%4];"
        : "=r"(r[0]), "=r"(r[1]), "=r"(r[2]), "=r"(r[3]) : "r"(addr));
}
__device__ __forceinline__ uint32_t pack_h2(float f0, float f1) {
    __half2 hh = __halves2half2(__float2half_rn(f0), __float2half_rn(f1));
    return *(uint32_t*)&hh;
}
// p = exp2(f16x2(s) + bias2) — result is the MMA-ready half2 fragment
__device__ __forceinline__ uint32_t exp2_pair(float s0, float s1, uint32_t bias2) {
    __half2 hv = __floats2half2_rn(s0, s1);
    hv = __hadd2(hv, *(__half2*)&bias2);
    hv = h2exp2(hv);
    return *(uint32_t*)&hv;
}
// fp32 sum of the two halves of (a + b)
__device__ __forceinline__ float hpair_sum(uint32_t a, uint32_t b) {
    __half2 s = __hadd2(*(__half2*)&a, *(__half2*)&b);
    float2 f = __half22float2(s);
    return f.x + f.y;
}

// ---------------------------------------------------------------------------
// GEMM core (verified round 12/13): plain fp16, acc = A@B^T, x4 ldmatrix.
// CTA tile 128x128, K-chunk 32, 3-stage cp.async, 8 warps (2x4), warp 64x32.
// ---------------------------------------------------------------------------
#define TM 128
#define TN 128
#define TK 32
#define PITCH 40
#define OAH 0
#define OBH 10240
#define STG 20480
#define NSTAGE 3
#define GSMEM (STG * NSTAGE)
#define NCH (H_ / TK)

__device__ __forceinline__ void gemm_core(
    const __half* __restrict__ Ah, const __half* __restrict__ Bh,
    int row0, int col0, char* gsm, float acc[4][4][4]) {

    const int tid = threadIdx.x;
    const int wid = tid >> 5;
    const int lane = tid & 31;
    const int li = lane & 7;
    const int wm = wid & 1;
    const int wn = wid >> 1;
    const uint32_t sb = smem_u32(gsm);

    const uint32_t aoff = (uint32_t)((wm * 64 + li + ((lane & 8) ? 8 : 0)) * 80)
                          + ((lane & 16) ? 16u : 0u);
    const uint32_t boff4 = (uint32_t)((wn * 32 + li + ((lane & 16) ? 8 : 0)) * 80)
                           + ((lane & 8) ? 16u : 0u);

    auto load_chunk = [&](int c, int s) {
        const int k0 = c * TK;
        const uint32_t base = sb + s * STG;
        #pragma unroll
        for (int i = 0; i < 2; i++) {
            int idx = tid + i * 256;
            int r = idx >> 2, c16 = idx & 3;
            uint32_t so = r * 80 + c16 * 16;
            cp16(base + OAH + so, Ah + (size_t)(row0 + r) * H_ + k0 + c16 * 8);
        }
        #pragma unroll
        for (int i = 0; i < 2; i++) {
            int idx = tid + i * 256;
            int r = idx >> 2, c16 = idx & 3;
            uint32_t so = r * 80 + c16 * 16;
            cp16(base + OBH + so, Bh + (size_t)(col0 + r) * H_ + k0 + c16 * 8);
        }
        cp_commit();
    };

    load_chunk(0, 0);
    load_chunk(1, 1);

    for (int c = 0; c < NCH; c++) {
        const int s = c % NSTAGE;
        if (c + 2 < NCH) load_chunk(c + 2, (c + 2) % NSTAGE);
        else cp_commit();
        asm volatile("cp.async.wait_group 2;" ::: "memory");
        __syncthreads();

        const uint32_t stb = sb + s * STG;

        #pragma unroll
        for (int ks = 0; ks < 2; ks++) {
            uint32_t ah[4][4], bh[4][2];
            #pragma unroll
            for (int mt = 0; mt < 4; mt++)
                ldsm_x4(ah[mt], stb + OAH + aoff + mt * 1280 + ks * 32);
            #pragma unroll
            for (int j = 0; j < 2; j++) {
                uint32_t tmp[4];
                ldsm_x4(tmp, stb + OBH + boff4 + j * 1280 + ks * 32);
                bh[2 * j][0] = tmp[0]; bh[2 * j][1] = tmp[1];
                bh[2 * j + 1][0] = tmp[2]; bh[2 * j + 1][1] = tmp[3];
            }
            #pragma unroll
            for (int mt = 0; mt < 4; mt++)
                #pragma unroll
                for (int nt = 0; nt < 4; nt++)
                    mma16816(acc[mt][nt], ah[mt], bh[nt]);
        }
        __syncthreads();
    }
}

// ---------------------------------------------------------------------------
// QKV projection GEMM. Q pre-scaled by 0.125*log2(e) (exp2-domain scores).
// ---------------------------------------------------------------------------
__global__ __launch_bounds__(256, 2)
void gemm_qkv() {
    extern __shared__ char gsm[];
    const int mode = blockIdx.z;
    const int row0 = blockIdx.y * TM;
    const int col0 = blockIdx.x * TN;

    float acc[4][4][4];
    #pragma unroll
    for (int i = 0; i < 4; i++)
        #pragma unroll
        for (int j = 0; j < 4; j++)
            #pragma unroll
            for (int q = 0; q < 4; q++) acc[i][j][q] = 0.f;

    gemm_core(g_Xh, g_WhT[mode], row0, col0, gsm, acc);

    const int tid = threadIdx.x;
    const int wid = tid >> 5;
    const int lane = tid & 31;
    const int gid = lane >> 2;
    const int t = lane & 3;
    const int wm = wid & 1;
    const int wn = wid >> 1;

    if (mode == 2) {
        __half* tile = (__half*)gsm;     // [128 cols][136] halves
        #pragma unroll
        for (int mt = 0; mt < 4; mt++)
            #pragma unroll
            for (int rr = 0; rr < 2; rr++) {
                const int rl = wm * 64 + mt * 16 + gid + rr * 8;
                #pragma unroll
                for (int nt = 0; nt < 4; nt++) {
                    const int cl = wn * 32 + nt * 8 + 2 * t;
                    tile[cl * 136 + rl]       = __float2half_rn(acc[mt][nt][rr * 2 + 0]);
                    tile[(cl + 1) * 136 + rl] = __float2half_rn(acc[mt][nt][rr * 2 + 1]);
                }
            }
        __syncthreads();
        const int bb = row0 >> 11;
        const int s0 = row0 & 2047;
        #pragma unroll
        for (int i = 0; i < 8; i++) {
            int idx = tid + i * 256;
            int r = idx >> 4, c8 = idx & 15;
            int hh = (col0 >> 6) + (r >> 6);
            int dd = r & 63;
            float4 v = *(const float4*)&tile[r * 136 + c8 * 8];
            *(float4*)(g_Vth + (((size_t)bb * NH_ + hh) * HD_ + dd) * S_ + s0 + c8 * 8) = v;
        }
    } else {
        __half* dst = (mode == 0) ? g_Qah : g_Kah;
        const float scl = (mode == 0) ? 0.1803368801111244f : 1.0f;  // 0.125*log2(e)
        #pragma unroll
        for (int mt = 0; mt < 4; mt++)
            #pragma unroll
            for (int rr = 0; rr < 2; rr++) {
                const int rg = row0 + wm * 64 + mt * 16 + gid + rr * 8;
                const int bb = rg >> 11;
                const int ss = rg & 2047;
                #pragma unroll
                for (int nt = 0; nt < 4; nt++) {
                    const int cg = col0 + wn * 32 + nt * 8 + 2 * t;
                    const int hh = cg >> 6, dd = cg & 63;
                    const size_t go = (((size_t)bb * NH_ + hh) * S_ + ss) * HD_ + dd;
                    *(uint32_t*)(dst + go) =
                        pack_h2(acc[mt][nt][rr * 2 + 0] * scl,
                                acc[mt][nt][rr * 2 + 1] * scl);
                }
            }
    }
}

// ---------------------------------------------------------------------------
// Output projection GEMM: out(fp32) = ctx(fp16) @ WO
// ---------------------------------------------------------------------------
__global__ __launch_bounds__(256, 2)
void gemm_o(float* __restrict__ out) {
    extern __shared__ char gsm[];
    const int row0 = blockIdx.y * TM;
    const int col0 = blockIdx.x * TN;

    float acc[4][4][4];
    #pragma unroll
    for (int i = 0; i < 4; i++)
        #pragma unroll
        for (int j = 0; j < 4; j++)
            #pragma unroll
            for (int q = 0; q < 4; q++) acc[i][j][q] = 0.f;

    gemm_core(g_Ch, g_WhT[3], row0, col0, gsm, acc);

    const int tid = threadIdx.x;
    const int wid = tid >> 5;
    const int lane = tid & 31;
    const int gid = lane >> 2;
    const int t = lane & 3;
    const int wm = wid & 1;
    const int wn = wid >> 1;

    #pragma unroll
    for (int mt = 0; mt < 4; mt++) {
        const int rg = row0 + wm * 64 + mt * 16 + gid;
        #pragma unroll
        for (int nt = 0; nt < 4; nt++) {
            const int cg = col0 + wn * 32 + nt * 8 + 2 * t;
            *(float2*)(out + (size_t)rg * H_ + cg) =
                make_float2(acc[mt][nt][0], acc[mt][nt][1]);
            *(float2*)(out + (size_t)(rg + 8) * H_ + cg) =
                make_float2(acc[mt][nt][2], acc[mt][nt][3]);
        }
    }
}

// ---------------------------------------------------------------------------
// Flash attention: 256 q-rows/CTA, exp2 no-max softmax, cross-tile pipelined
// QK(t+1)/exp2(t)/PV(t). l computed from p fragments via half2 sums on the
// idle fma/alu pipes (tensor-core l-MMA removed: 72 -> 64 MMAs per tile).
// ---------------------------------------------------------------------------
#define FROWB 144
#define SQH   0                  // Q: 256*144 = 36864
#define SK0   36864              // K bufs: 2 x 9216
#define SV0   55296              // V bufs: 3 x 9216
#define SMK   82944              // bias halves: 3 bufs x 128B
#define FSMEM 83328

__global__ __launch_bounds__(256, 1)
void flash_mma(const int* __restrict__ mask) {
    extern __shared__ char sm[];
    const int tid = threadIdx.x;
    const int wid = tid >> 5;
    const int lane = tid & 31;
    const int li = lane & 7;
    const int gid = lane >> 2;
    const int tq = lane & 3;
    const int q0 = blockIdx.x * 256;
    const int h = blockIdx.y;
    const int b = blockIdx.z;
    const size_t bh = (size_t)b * NH_ + h;

    const __half* Qhp = g_Qah + (bh * S_ + q0) * HD_;
    const __half* Khp = g_Kah + bh * S_ * HD_;
    const __half* Vtp = g_Vth + bh * HD_ * S_;
    const int* mkp = mask + b * S_;

    const uint32_t sb = smem_u32(sm);
    const int m0r = wid * 32;

    const uint32_t q_lrow = (uint32_t)((li + ((lane & 8) ? 8 : 0)) * FROWB)
                            + ((lane & 16) ? 16u : 0u);
    const uint32_t kv4_loff = (uint32_t)((li + ((lane & 16) ? 8 : 0)) * FROWB)
                              + ((lane & 8) ? 16u : 0u);

    // Q load                              -> group 0
    #pragma unroll
    for (int i = 0; i < 8; i++) {
        int idx = tid + i * 256;
        int r = idx >> 3, c = idx & 7;
        cp16(sb + SQH + r * FROWB + c * 16, Qhp + (size_t)r * HD_ + c * 8);
    }
    cp_commit();

    auto load_kv = [&](int tile) {
        const int kv0 = tile * 64;
        const uint32_t kbb = sb + SK0 + (tile & 1) * 9216;
        const uint32_t vbb = sb + SV0 + (tile % 3) * 9216;
        #pragma unroll
        for (int i = 0; i < 2; i++) {
            int idx = tid + i * 256;
            int r = idx >> 3, c = idx & 7;
            uint32_t so = r * FROWB + c * 16;
            cp16(kbb + so, Khp + (size_t)(kv0 + r) * HD_ + c * 8);
            cp16(vbb + so, Vtp + (size_t)r * S_ + kv0 + c * 8);
        }
        if (tid < 64) {
            __half bias = (mkp[kv0 + tid] == 0) ? __ushort_as_half(0xFC00u)
                                                : __ushort_as_half(0u);
            *(__half*)(sm + SMK + (tile % 3) * 128 + tid * 2) = bias;
        }
        cp_commit();
    };

    load_kv(0);                           // group 1
    load_kv(1);                           // group 2
    asm volatile("cp.async.wait_group 1;" ::: "memory");   // Q + load0 done
    __syncthreads();

    // Hoist Q fragments
    uint32_t qf[2][4][4];
    #pragma unroll
    for (int mi = 0; mi < 2; mi++)
        #pragma unroll
        for (int ks = 0; ks < 4; ks++)
            ldsm_x4(qf[mi][ks],
                    sb + SQH + (uint32_t)((m0r + mi * 16) * FROWB) + q_lrow + ks * 32);

    float sc[2][8][4], ctx[2][8][4];
    float lr[2][2];                       // fp32 l accum: [mi][row r / r+8]
    #pragma unroll
    for (int mi = 0; mi < 2; mi++) {
        #pragma unroll
        for (int nt = 0; nt < 8; nt++)
            #pragma unroll
            for (int e = 0; e < 4; e++) { sc[mi][nt][e] = 0.f; ctx[mi][nt][e] = 0.f; }
        lr[mi][0] = 0.f; lr[mi][1] = 0.f;
    }

    // QK(0) standalone (j = kk outer, ks inner)
    {
        const uint32_t kb0 = sb + SK0;
        #pragma unroll
        for (int kk = 0; kk < 4; kk++)
            #pragma unroll
            for (int ks = 0; ks < 4; ks++) {
                uint32_t tmp[4];
                ldsm_x4(tmp, kb0 + kv4_loff + kk * 2304 + ks * 32);
                #pragma unroll
                for (int mi = 0; mi < 2; mi++) {
                    mma16816(sc[mi][2 * kk],     qf[mi][ks], tmp);
                    mma16816(sc[mi][2 * kk + 1], qf[mi][ks], tmp + 2);
                }
            }
    }

    for (int tile = 0; tile < 32; tile++) {
        asm volatile("cp.async.wait_group 0;" ::: "memory");  // load(tile+1) done
        __syncthreads();
        if (tile + 2 < 32) load_kv(tile + 2);

        const uint32_t kbN = sb + SK0 + ((tile + 1) & 1) * 9216;  // K(t+1)
        const uint32_t vbC = sb + SV0 + (tile % 3) * 9216;        // V(t)
        const char* mkb = sm + SMK + (tile % 3) * 128;
        const bool do_qk = (tile < 31);

        #pragma unroll
        for (int kk = 0; kk < 4; kk++) {
            uint32_t bias_a = *(const uint32_t*)(mkb + ((2 * kk) * 8 + 2 * tq) * 2);
            uint32_t bias_b = *(const uint32_t*)(mkb + ((2 * kk + 1) * 8 + 2 * tq) * 2);
            uint32_t aph[2][4];
            #pragma unroll
            for (int mi = 0; mi < 2; mi++) {
                aph[mi][0] = exp2_pair(sc[mi][2 * kk][0],     sc[mi][2 * kk][1],     bias_a);
                aph[mi][1] = exp2_pair(sc[mi][2 * kk][2],     sc[mi][2 * kk][3],     bias_a);
                aph[mi][2] = exp2_pair(sc[mi][2 * kk + 1][0], sc[mi][2 * kk + 1][1], bias_b);
                aph[mi][3] = exp2_pair(sc[mi][2 * kk + 1][2], sc[mi][2 * kk + 1][3], bias_b);
                // l partial sums on fma/alu pipes (was a tensor-core MMA)
                lr[mi][0] += hpair_sum(aph[mi][0], aph[mi][2]);   // row r
                lr[mi][1] += hpair_sum(aph[mi][1], aph[mi][3]);   // row r+8
            }
            // QK(t+1) for n-tiles 2kk,2kk+1 — refills the sc slots just freed
            if (do_qk) {
                #pragma unroll
                for (int mi = 0; mi < 2; mi++)
                    #pragma unroll
                    for (int e = 0; e < 4; e++) {
                        sc[mi][2 * kk][e] = 0.f;
                        sc[mi][2 * kk + 1][e] = 0.f;
                    }
                #pragma unroll
                for (int ks = 0; ks < 4; ks++) {
                    uint32_t tmp[4];
                    ldsm_x4(tmp, kbN + kv4_loff + kk * 2304 + ks * 32);
                    #pragma unroll
                    for (int mi = 0; mi < 2; mi++) {
                        mma16816(sc[mi][2 * kk],     qf[mi][ks], tmp);
                        mma16816(sc[mi][2 * kk + 1], qf[mi][ks], tmp + 2);
                    }
                }
            }
            // PV(t), k-chunk kk
            #pragma unroll
            for (int j = 0; j < 4; j++) {
                uint32_t tmp[4];
                ldsm_x4(tmp, vbC + kv4_loff + j * 2304 + kk * 32);
                #pragma unroll
                for (int mi = 0; mi < 2; mi++) {
                    mma16816(ctx[mi][2 * j],     aph[mi], tmp);
                    mma16816(ctx[mi][2 * j + 1], aph[mi], tmp + 2);
                }
            }
        }
    }

    // Epilogue: complete l across the quad (t lanes cover disjoint columns).
    #pragma unroll
    for (int mi = 0; mi < 2; mi++) {
        lr[mi][0] += __shfl_xor_sync(0xffffffffu, lr[mi][0], 1);
        lr[mi][0] += __shfl_xor_sync(0xffffffffu, lr[mi][0], 2);
        lr[mi][1] += __shfl_xor_sync(0xffffffffu, lr[mi][1], 1);
        lr[mi][1] += __shfl_xor_sync(0xffffffffu, lr[mi][1], 2);
        const float inv0 = 1.f / lr[mi][0];
        const float inv1 = 1.f / lr[mi][1];
        const int r0 = b * S_ + q0 + m0r + mi * 16 + gid;
        #pragma unroll
        for (int nt = 0; nt < 8; nt++) {
            const int d0 = h * HD_ + nt * 8 + 2 * tq;
            *(uint32_t*)(g_Ch + (size_t)r0 * H_ + d0) =
                pack_h2(ctx[mi][nt][0] * inv0, ctx[mi][nt][1] * inv0);
            *(uint32_t*)(g_Ch + (size_t)(r0 + 8) * H_ + d0) =
                pack_h2(ctx[mi][nt][2] * inv1, ctx[mi][nt][3] * inv1);
        }
    }
}

// ---------------------------------------------------------------------------
// X convert: fp32 -> fp16
// ---------------------------------------------------------------------------
__global__ void xcvt(const float* __restrict__ A, int n4) {
    int i = blockIdx.x * blockDim.x + threadIdx.x;
    if (i >= n4) return;
    float4 v = ((const float4*)A)[i];
    ((uint32_t*)g_Xh)[2 * i + 0] = pack_h2(v.x, v.y);
    ((uint32_t*)g_Xh)[2 * i + 1] = pack_h2(v.z, v.w);
}

// ---------------------------------------------------------------------------
// Weight convert+transpose: W[K,N] fp32 -> WhT[z][N,K] fp16
// ---------------------------------------------------------------------------
__global__ void wcvt_t(const float* __restrict__ W0, const float* __restrict__ W1,
                       const float* __restrict__ W2, const float* __restrict__ W3) {
    __shared__ float tbuf[32][33];
    const int z = blockIdx.z;
    const float* W = (z == 0) ? W0 : (z == 1) ? W1 : (z == 2) ? W2 : W3;
    __half* O = g_WhT[z];
    int n0 = blockIdx.x * 32, k0 = blockIdx.y * 32;
    int x = threadIdx.x, y0 = threadIdx.y;
    #pragma unroll
    for (int i = y0; i < 32; i += 8)
        tbuf[i][x] = W[(size_t)(k0 + i) * H_ + n0 + x];
    __syncthreads();
    #pragma unroll
    for (int i = y0; i < 32; i += 8)
        O[(size_t)(n0 + i) * H_ + k0 + x] = __float2half_rn(tbuf[x][i]);
}

// ---------------------------------------------------------------------------
// Launch (flash_mma stays launch #4 -> ncu capture window)
// ---------------------------------------------------------------------------
extern "C" void kernel_launch(void* const* d_in, const int* in_sizes, int n_in,
                              void* d_out, int out_size) {
    const float* X    = (const float*)d_in[0];
    const int*   mask = (const int*)d_in[1];
    const float* WQ   = (const float*)d_in[2];
    const float* WK   = (const float*)d_in[3];
    const float* WV   = (const float*)d_in[4];
    const float* WO   = (const float*)d_in[5];
    float* out = (float*)d_out;

    cudaFuncSetAttribute(gemm_qkv, cudaFuncAttributeMaxDynamicSharedMemorySize, GSMEM);
    cudaFuncSetAttribute(gemm_o,   cudaFuncAttributeMaxDynamicSharedMemorySize, GSMEM);
    cudaFuncSetAttribute(flash_mma, cudaFuncAttributeMaxDynamicSharedMemorySize, FSMEM);

    // 1. Prep
    xcvt<<<(M_ * H_ / 4 + 255) / 256, 256>>>(X, M_ * H_ / 4);
    // 2.
    wcvt_t<<<dim3(32, 32, 4), dim3(32, 8)>>>(WQ, WK, WV, WO);
    // 3. QKV projections (Q pre-scaled into exp2 domain)
    gemm_qkv<<<dim3(H_ / TN, M_ / TM, 3), 256, GSMEM>>>();
    // 4. Attention (pipelined; l on fma/alu pipes)
    flash_mma<<<dim3(S_ / 256, NH_, B_), 256, FSMEM>>>(mask);
    // 5. Output projection
    gemm_o<<<dim3(H_ / TN, M_ / TM), 256, GSMEM>>>(out);
}